// round 15
// baseline (speedup 1.0000x reference)
#include <cuda_runtime.h>
#include <cstdint>

// AtteMatchLay via mma.sync TF32 + 4-deep cp.async pipeline.
// R15 = R11 carrier (rolled mainloop, dynamic stage index; best measured
// scheduling: issue 36%) + R13's verified CVT deletion (raw fp32 bits into
// the tf32 MMA; HW truncates low 13 mantissa bits; cosine ratio cancels the
// systematic bias -> rel_err ~3e-4). Nothing else changed.
//   dot = (r*m) @ w2^T, n1^2 = (r*r) @ w2^T, n2^2 = (m*m) @ w2^T
//   cos = dot / (max(sqrt(n1^2),eps) * max(sqrt(n2^2),eps))
// 256 CTAs x 32 rows, 8 warps = 2 row-strips x 4 K-quarters.
// Per chunk (64 K): cp.async stages r, m ([32][68]) and raw W slice
// ([24][68], rows 20..23 zero-filled) -> 23936 B/stage, 4 stages (95744 B).

static constexpr int D        = 768;
static constexpr int P        = 20;
static constexpr int NPAD     = 24;
static constexpr int ROWS_CTA = 32;
static constexpr int THREADS  = 256;
static constexpr int NROWS    = 8192;
static constexpr int NCTA     = NROWS / ROWS_CTA;   // 256
static constexpr int KCH      = 64;
static constexpr int NCHUNK   = D / KCH;            // 12
static constexpr int STAGES   = 4;

static constexpr int SA = 68;                        // row stride (floats), conflict-free
static constexpr int A_ARR   = ROWS_CTA * SA * 4;    // 8704 B per array (r or m)
static constexpr int B_ARR   = NPAD * SA * 4;        // 6528 B (raw W slice [n][k])
static constexpr int B_ITEMS = NPAD * 16;            // 384 float4 of actual data
static constexpr int STG_B   = 2 * A_ARR + B_ARR;    // 23936 B
static constexpr int SMEM_TOTAL = STAGES * STG_B;    // 95744 B -> 2 CTAs/SM

// epilogue aliases (after mainloop + syncthreads)
static constexpr int OFF_RED = 0;       // 2*3*36*32*4 = 27648 B
static constexpr int OFF_OUT = 28672;   // 32*20*4 = 2560 B

__device__ __forceinline__ uint32_t smem_u32(const void* p) {
    uint32_t a;
    asm("{ .reg .u64 t; cvta.to.shared.u64 t, %1; cvt.u32.u64 %0, t; }" : "=r"(a) : "l"(p));
    return a;
}
__device__ __forceinline__ void cp16(uint32_t dst, const void* src) {
    asm volatile("cp.async.cg.shared.global [%0], [%1], 16;" :: "r"(dst), "l"(src));
}
// predicated source: srcbytes=0 -> zero-fill 16 bytes (no global read)
__device__ __forceinline__ void cp16p(uint32_t dst, const void* src, int srcbytes) {
    asm volatile("cp.async.cg.shared.global [%0], [%1], 16, %2;"
                 :: "r"(dst), "l"(src), "r"(srcbytes));
}
__device__ __forceinline__ void cp_commit() {
    asm volatile("cp.async.commit_group;" ::: "memory");
}
template <int N>
__device__ __forceinline__ void cp_wait() {
    asm volatile("cp.async.wait_group %0;" :: "n"(N) : "memory");
}
__device__ __forceinline__ void mma8(float* d, const uint32_t* a, uint32_t b0, uint32_t b1) {
    asm volatile(
        "mma.sync.aligned.m16n8k8.row.col.f32.tf32.tf32.f32 "
        "{%0,%1,%2,%3}, {%4,%5,%6,%7}, {%8,%9}, {%0,%1,%2,%3};"
        : "+f"(d[0]), "+f"(d[1]), "+f"(d[2]), "+f"(d[3])
        : "r"(a[0]), "r"(a[1]), "r"(a[2]), "r"(a[3]), "r"(b0), "r"(b1));
}

__global__ void __launch_bounds__(THREADS, 2)
amatch_mma(const float* __restrict__ R, const float* __restrict__ Mx,
           const float* __restrict__ W, float* __restrict__ out)
{
    extern __shared__ char smem[];
    const uint32_t sb = smem_u32(smem);

    const int tid   = threadIdx.x;
    const int lane  = tid & 31;
    const int wid   = tid >> 5;
    const int g     = lane >> 2;
    const int t     = lane & 3;
    const int strip = wid >> 2;
    const int kq    = wid & 3;
    const int row0  = blockIdx.x * ROWS_CTA;

    // staging thread mapping (A): 512 float4 per array per chunk, 2 per thread
    const int srow0 = tid >> 4;          // rows tid>>4 and tid>>4 + 16
    const int sk4   = (tid & 15) << 2;   // k offset in floats (0,4,...,60)

    auto issue_stage = [&](int c, int s) {
        const uint32_t stg = sb + (uint32_t)s * STG_B;
        const size_t gofs = (size_t)row0 * D + (size_t)c * KCH;
        // A: r and m, 2 rows per thread
#pragma unroll
        for (int i = 0; i < 2; i++) {
            const int row = srow0 + i * 16;
            const size_t go = gofs + (size_t)row * D + sk4;
            const uint32_t so = (uint32_t)(row * SA + sk4) * 4u;
            cp16(stg + so,         R  + go);
            cp16(stg + A_ARR + so, Mx + go);
        }
        // B: raw W slice, 24 rows x 16 float4 = 384 items over 256 threads;
        // rows >= 20 zero-filled (no OOB read)
#pragma unroll
        for (int i = tid; i < B_ITEMS; i += THREADS) {
            const int n  = i >> 4;
            const int k4 = (i & 15) << 2;
            const int nv = (n < P) ? n : 0;
            const size_t go = (size_t)nv * D + (size_t)c * KCH + k4;
            const uint32_t so = (uint32_t)(2 * A_ARR) + (uint32_t)(n * SA + k4) * 4u;
            cp16p(stg + so, W + go, (n < P) ? 16 : 0);
        }
        cp_commit();
    };

    float acc[3][3][4];   // [type: rm/rr/mm][ntile][cfrag]
#pragma unroll
    for (int a = 0; a < 3; a++)
#pragma unroll
        for (int b = 0; b < 3; b++)
#pragma unroll
            for (int j = 0; j < 4; j++) acc[a][b][j] = 0.f;

    // prologue: fill stages 0..2
#pragma unroll
    for (int s = 0; s < STAGES - 1; s++) issue_stage(s, s);

    int sidx = 0;   // c % STAGES  (rolled loop: dynamic, preserves R11 scheduling)
    for (int c = 0; c < NCHUNK; ++c) {
        // chunk c complete when pending groups <= min(2, 11-c)
        if (c <= NCHUNK - 3)      cp_wait<2>();
        else if (c == NCHUNK - 2) cp_wait<1>();
        else                      cp_wait<0>();
        __syncthreads();

        if (c + STAGES - 1 < NCHUNK) {
            int s2 = sidx + STAGES - 1;
            if (s2 >= STAGES) s2 -= STAGES;
            issue_stage(c + STAGES - 1, s2);
        }

        const char* stg = smem + sidx * STG_B;
        const float* sr = reinterpret_cast<const float*>(stg);
        const float* sm = reinterpret_cast<const float*>(stg + A_ARR);
        const float* sw = reinterpret_cast<const float*>(stg + 2 * A_ARR);

#pragma unroll
        for (int it = 0; it < 2; it++) {
            const int kl = kq * 16 + it * 8 + t;   // k within chunk

            const int i0 = (strip * 16 + g) * SA + kl;
            const int i1 = i0 + 8 * SA;
            const float r0 = sr[i0], r1 = sr[i1], r2 = sr[i0 + 4], r3 = sr[i1 + 4];
            const float m0 = sm[i0], m1 = sm[i1], m2 = sm[i0 + 4], m3 = sm[i1 + 4];

            // raw fp32 bits; tf32 MMA truncates low 13 mantissa bits (RZ)
            uint32_t arm[4] = { __float_as_uint(r0 * m0), __float_as_uint(r1 * m1),
                                __float_as_uint(r2 * m2), __float_as_uint(r3 * m3) };
            uint32_t arr[4] = { __float_as_uint(r0 * r0), __float_as_uint(r1 * r1),
                                __float_as_uint(r2 * r2), __float_as_uint(r3 * r3) };
            uint32_t amm[4] = { __float_as_uint(m0 * m0), __float_as_uint(m1 * m1),
                                __float_as_uint(m2 * m2), __float_as_uint(m3 * m3) };

#pragma unroll
            for (int nt = 0; nt < 3; nt++) {
                const float w0 = sw[(nt * 8 + g) * SA + kl];
                const float w1 = sw[(nt * 8 + g) * SA + kl + 4];
                const uint32_t b0 = __float_as_uint(w0 * w0);
                const uint32_t b1 = __float_as_uint(w1 * w1);
                mma8(acc[0][nt], arm, b0, b1);
                mma8(acc[1][nt], arr, b0, b1);
                mma8(acc[2][nt], amm, b0, b1);
            }
        }

        if (++sidx == STAGES) sidx = 0;
    }
    __syncthreads();   // all warps done with stage buffers before aliasing

    // ---- reduce over the 4 K-quarter warps per strip ----
    float* s_red = reinterpret_cast<float*>(smem + OFF_RED);
    if (kq > 0) {
        float* dst = s_red + (size_t)(strip * 3 + (kq - 1)) * 36 * 32 + lane;
#pragma unroll
        for (int a = 0; a < 3; a++)
#pragma unroll
            for (int b = 0; b < 3; b++)
#pragma unroll
                for (int j = 0; j < 4; j++)
                    dst[((a * 3 + b) * 4 + j) * 32] = acc[a][b][j];
    }
    __syncthreads();

    float* s_out = reinterpret_cast<float*>(smem + OFF_OUT);
    if (kq == 0) {
#pragma unroll
        for (int s2 = 0; s2 < 3; s2++) {
            const float* src = s_red + (size_t)(strip * 3 + s2) * 36 * 32 + lane;
#pragma unroll
            for (int a = 0; a < 3; a++)
#pragma unroll
                for (int b = 0; b < 3; b++)
#pragma unroll
                    for (int j = 0; j < 4; j++)
                        acc[a][b][j] += src[((a * 3 + b) * 4 + j) * 32];
        }
        const float EPS = 1e-8f;
#pragma unroll
        for (int nt = 0; nt < 3; nt++) {
#pragma unroll
            for (int j = 0; j < 4; j++) {
                const int col = nt * 8 + 2 * t + (j & 1);
                const int row = strip * 16 + g + (j >> 1) * 8;
                if (col < P) {
                    const float dot = acc[0][nt][j];
                    const float a2  = acc[1][nt][j];
                    const float b2  = acc[2][nt][j];
                    s_out[row * P + col] =
                        dot / (fmaxf(sqrtf(a2), EPS) * fmaxf(sqrtf(b2), EPS));
                }
            }
        }
    }
    __syncthreads();

    // ---- coalesced store: 640 floats = 160 float4 ----
    if (tid < ROWS_CTA * P / 4) {
        float4 v = *reinterpret_cast<float4*>(s_out + tid * 4);
        *reinterpret_cast<float4*>(out + (size_t)row0 * P + tid * 4) = v;
    }
}

extern "C" void kernel_launch(void* const* d_in, const int* in_sizes, int n_in,
                              void* d_out, int out_size)
{
    const float* repres  = (const float*)d_in[0];
    const float* max_att = (const float*)d_in[1];
    const float* weight  = (const float*)d_in[2];
    float* out = (float*)d_out;

    cudaFuncSetAttribute(amatch_mma,
                         cudaFuncAttributeMaxDynamicSharedMemorySize, SMEM_TOTAL);

    amatch_mma<<<NCTA, THREADS, SMEM_TOTAL>>>(repres, max_att, weight, out);
}

// round 16
// speedup vs baseline: 1.1073x; 1.1073x over previous
#include <cuda_runtime.h>
#include <cstdint>

// AtteMatchLay via mma.sync TF32 + cp.async, 12-warp-CTA version (R16).
//   dot = (r*m) @ w2^T, n1^2 = (r*r) @ w2^T, n2^2 = (m*m) @ w2^T
//   cos = dot / (max(sqrt(n1^2),eps) * max(sqrt(n2^2),eps))
// 256 CTAs x 32 rows, 384 threads = 12 warps = 2 row-strips x 6 K-sixths.
// KCH=96 (NCHUNK=8), 3 stages x 35200 B = 105600 B -> 2 CTAs/SM, 24 warps
// on binding SMs (vs 16 in R11) with IDENTICAL per-warp instruction
// structure (the R12 lesson: add warps only at constant instrs/MAC).
// Per chunk: cp.async stages r, m ([32][100]) and raw W slice ([24][100],
// rows 20..23 zero-filled); w^2 + cvt.rna at fragment read (CVT kept -- R15
// measured that removing it costs +5.5us).

static constexpr int D        = 768;
static constexpr int P        = 20;
static constexpr int NPAD     = 24;
static constexpr int ROWS_CTA = 32;
static constexpr int THREADS  = 384;
static constexpr int NROWS    = 8192;
static constexpr int NCTA     = NROWS / ROWS_CTA;   // 256
static constexpr int KCH      = 96;
static constexpr int NCHUNK   = D / KCH;            // 8
static constexpr int STAGES   = 3;

static constexpr int SA = 100;                       // row stride (floats): banks 4g+t, conflict-free
static constexpr int A_ARR   = ROWS_CTA * SA * 4;    // 12800 B per array (r or m)
static constexpr int B_ARR   = NPAD * SA * 4;        // 9600 B (raw W slice [n][k])
static constexpr int A_ITEMS = ROWS_CTA * (KCH / 4); // 768 float4 per array
static constexpr int B_ITEMS = NPAD * (KCH / 4);     // 576 float4
static constexpr int STG_B   = 2 * A_ARR + B_ARR;    // 35200 B
static constexpr int SMEM_TOTAL = STAGES * STG_B;    // 105600 B -> 2 CTAs/SM

// epilogue aliases (after mainloop + syncthreads)
static constexpr int OFF_RED = 0;       // 2 strips * 5 slots * 36*32*4 = 46080 B
static constexpr int OFF_OUT = 46080;   // 32*20*4 = 2560 B

__device__ __forceinline__ uint32_t f2tf32(float x) {
    uint32_t t;
    asm("cvt.rna.tf32.f32 %0, %1;" : "=r"(t) : "f"(x));
    return t;
}
__device__ __forceinline__ uint32_t smem_u32(const void* p) {
    uint32_t a;
    asm("{ .reg .u64 t; cvta.to.shared.u64 t, %1; cvt.u32.u64 %0, t; }" : "=r"(a) : "l"(p));
    return a;
}
__device__ __forceinline__ void cp16(uint32_t dst, const void* src) {
    asm volatile("cp.async.cg.shared.global [%0], [%1], 16;" :: "r"(dst), "l"(src));
}
// predicated source: srcbytes=0 -> zero-fill 16 bytes (no global read)
__device__ __forceinline__ void cp16p(uint32_t dst, const void* src, int srcbytes) {
    asm volatile("cp.async.cg.shared.global [%0], [%1], 16, %2;"
                 :: "r"(dst), "l"(src), "r"(srcbytes));
}
__device__ __forceinline__ void cp_commit() {
    asm volatile("cp.async.commit_group;" ::: "memory");
}
template <int N>
__device__ __forceinline__ void cp_wait() {
    asm volatile("cp.async.wait_group %0;" :: "n"(N) : "memory");
}
__device__ __forceinline__ void mma8(float* d, const uint32_t* a, uint32_t b0, uint32_t b1) {
    asm volatile(
        "mma.sync.aligned.m16n8k8.row.col.f32.tf32.tf32.f32 "
        "{%0,%1,%2,%3}, {%4,%5,%6,%7}, {%8,%9}, {%0,%1,%2,%3};"
        : "+f"(d[0]), "+f"(d[1]), "+f"(d[2]), "+f"(d[3])
        : "r"(a[0]), "r"(a[1]), "r"(a[2]), "r"(a[3]), "r"(b0), "r"(b1));
}

__global__ void __launch_bounds__(THREADS, 2)
amatch_mma(const float* __restrict__ R, const float* __restrict__ Mx,
           const float* __restrict__ W, float* __restrict__ out)
{
    extern __shared__ char smem[];
    const uint32_t sb = smem_u32(smem);

    const int tid   = threadIdx.x;
    const int lane  = tid & 31;
    const int wid   = tid >> 5;      // 0..11
    const int g     = lane >> 2;
    const int t     = lane & 3;
    const int strip = wid / 6;       // 0/1: which 16-row strip
    const int kq    = wid % 6;       // K sixth (16 k each)
    const int row0  = blockIdx.x * ROWS_CTA;

    auto issue_stage = [&](int c, int s) {
        const uint32_t stg = sb + (uint32_t)s * STG_B;
        const size_t gofs = (size_t)row0 * D + (size_t)c * KCH;
        // A: r and m, 768 float4 per array over 384 threads (2 each)
#pragma unroll
        for (int i = 0; i < 2; i++) {
            const int idx = i * THREADS + tid;      // 0..767
            const int row = idx / (KCH / 4);
            const int k4  = (idx % (KCH / 4)) << 2;
            const size_t go = gofs + (size_t)row * D + k4;
            const uint32_t so = (uint32_t)(row * SA + k4) * 4u;
            cp16(stg + so,         R  + go);
            cp16(stg + A_ARR + so, Mx + go);
        }
        // B: raw W slice, 576 float4 over 384 threads; rows >= 20 zero-filled
        for (int i = tid; i < B_ITEMS; i += THREADS) {
            const int n  = i / (KCH / 4);
            const int k4 = (i % (KCH / 4)) << 2;
            const int nv = (n < P) ? n : 0;
            const size_t go = (size_t)nv * D + (size_t)c * KCH + k4;
            const uint32_t so = (uint32_t)(2 * A_ARR) + (uint32_t)(n * SA + k4) * 4u;
            cp16p(stg + so, W + go, (n < P) ? 16 : 0);
        }
        cp_commit();
    };

    float acc[3][3][4];   // [type: rm/rr/mm][ntile][cfrag]
#pragma unroll
    for (int a = 0; a < 3; a++)
#pragma unroll
        for (int b = 0; b < 3; b++)
#pragma unroll
            for (int j = 0; j < 4; j++) acc[a][b][j] = 0.f;

    // prologue: fill stages 0..1
#pragma unroll
    for (int s = 0; s < STAGES - 1; s++) issue_stage(s, s);

    int sidx = 0;   // c % STAGES
    for (int c = 0; c < NCHUNK; ++c) {
        // chunk c complete when pending groups <= min(1, NCHUNK-1-c)
        if (c < NCHUNK - 1) cp_wait<1>();
        else                cp_wait<0>();
        __syncthreads();

        if (c + STAGES - 1 < NCHUNK) {
            int s2 = sidx + STAGES - 1;
            if (s2 >= STAGES) s2 -= STAGES;
            issue_stage(c + STAGES - 1, s2);
        }

        const char* stg = smem + sidx * STG_B;
        const float* sr = reinterpret_cast<const float*>(stg);
        const float* sm = reinterpret_cast<const float*>(stg + A_ARR);
        const float* sw = reinterpret_cast<const float*>(stg + 2 * A_ARR);

#pragma unroll
        for (int it = 0; it < 2; it++) {
            const int kl = kq * 16 + it * 8 + t;   // k within chunk

            const int i0 = (strip * 16 + g) * SA + kl;
            const int i1 = i0 + 8 * SA;
            const float r0 = sr[i0], r1 = sr[i1], r2 = sr[i0 + 4], r3 = sr[i1 + 4];
            const float m0 = sm[i0], m1 = sm[i1], m2 = sm[i0 + 4], m3 = sm[i1 + 4];

            uint32_t arm[4] = { f2tf32(r0 * m0), f2tf32(r1 * m1), f2tf32(r2 * m2), f2tf32(r3 * m3) };
            uint32_t arr[4] = { f2tf32(r0 * r0), f2tf32(r1 * r1), f2tf32(r2 * r2), f2tf32(r3 * r3) };
            uint32_t amm[4] = { f2tf32(m0 * m0), f2tf32(m1 * m1), f2tf32(m2 * m2), f2tf32(m3 * m3) };

#pragma unroll
            for (int nt = 0; nt < 3; nt++) {
                const float w0 = sw[(nt * 8 + g) * SA + kl];
                const float w1 = sw[(nt * 8 + g) * SA + kl + 4];
                const uint32_t b0 = f2tf32(w0 * w0);
                const uint32_t b1 = f2tf32(w1 * w1);
                mma8(acc[0][nt], arm, b0, b1);
                mma8(acc[1][nt], arr, b0, b1);
                mma8(acc[2][nt], amm, b0, b1);
            }
        }

        if (++sidx == STAGES) sidx = 0;
    }
    __syncthreads();   // all warps done with stage buffers before aliasing

    // ---- reduce over the 6 K-sixth warps per strip ----
    float* s_red = reinterpret_cast<float*>(smem + OFF_RED);
    if (kq > 0) {
        float* dst = s_red + (size_t)(strip * 5 + (kq - 1)) * 36 * 32 + lane;
#pragma unroll
        for (int a = 0; a < 3; a++)
#pragma unroll
            for (int b = 0; b < 3; b++)
#pragma unroll
                for (int j = 0; j < 4; j++)
                    dst[((a * 3 + b) * 4 + j) * 32] = acc[a][b][j];
    }
    __syncthreads();

    float* s_out = reinterpret_cast<float*>(smem + OFF_OUT);
    if (kq == 0) {
#pragma unroll
        for (int s2 = 0; s2 < 5; s2++) {
            const float* src = s_red + (size_t)(strip * 5 + s2) * 36 * 32 + lane;
#pragma unroll
            for (int a = 0; a < 3; a++)
#pragma unroll
                for (int b = 0; b < 3; b++)
#pragma unroll
                    for (int j = 0; j < 4; j++)
                        acc[a][b][j] += src[((a * 3 + b) * 4 + j) * 32];
        }
        const float EPS = 1e-8f;
#pragma unroll
        for (int nt = 0; nt < 3; nt++) {
#pragma unroll
            for (int j = 0; j < 4; j++) {
                const int col = nt * 8 + 2 * t + (j & 1);
                const int row = strip * 16 + g + (j >> 1) * 8;
                if (col < P) {
                    const float dot = acc[0][nt][j];
                    const float a2  = acc[1][nt][j];
                    const float b2  = acc[2][nt][j];
                    s_out[row * P + col] =
                        dot / (fmaxf(sqrtf(a2), EPS) * fmaxf(sqrtf(b2), EPS));
                }
            }
        }
    }
    __syncthreads();

    // ---- coalesced store: 640 floats = 160 float4 ----
    if (tid < ROWS_CTA * P / 4) {
        float4 v = *reinterpret_cast<float4*>(s_out + tid * 4);
        *reinterpret_cast<float4*>(out + (size_t)row0 * P + tid * 4) = v;
    }
}

extern "C" void kernel_launch(void* const* d_in, const int* in_sizes, int n_in,
                              void* d_out, int out_size)
{
    const float* repres  = (const float*)d_in[0];
    const float* max_att = (const float*)d_in[1];
    const float* weight  = (const float*)d_in[2];
    float* out = (float*)d_out;

    cudaFuncSetAttribute(amatch_mma,
                         cudaFuncAttributeMaxDynamicSharedMemorySize, SMEM_TOTAL);

    amatch_mma<<<NCTA, THREADS, SMEM_TOTAL>>>(repres, max_att, weight, out);
}

// round 17
// speedup vs baseline: 1.1969x; 1.0809x over previous
#include <cuda_runtime.h>
#include <cstdint>

// AtteMatchLay via mma.sync TF32 + cp.async, 12-warp CTA (R16 geometry) with
// chunk-invariant staging math hoisted out of the mainloop (R17).
//   dot = (r*m) @ w2^T, n1^2 = (r*r) @ w2^T, n2^2 = (m*m) @ w2^T
//   cos = dot / (max(sqrt(n1^2),eps) * max(sqrt(n2^2),eps))
// 256 CTAs x 32 rows, 384 threads = 12 warps = 2 row-strips x 6 K-sixths.
// KCH=96 (NCHUNK=8), 3 stages x 35200 B -> 2 CTAs/SM (24 warps on binding SMs).
// R17 fix: R16's staging div/mod by 24 (non-pow2) ran inside issue_stage per
// chunk -> alu pipe 20.2%. All indices are chunk-invariant; precompute once.

static constexpr int D        = 768;
static constexpr int P        = 20;
static constexpr int NPAD     = 24;
static constexpr int ROWS_CTA = 32;
static constexpr int THREADS  = 384;
static constexpr int NROWS    = 8192;
static constexpr int NCTA     = NROWS / ROWS_CTA;   // 256
static constexpr int KCH      = 96;
static constexpr int NCHUNK   = D / KCH;            // 8
static constexpr int STAGES   = 3;
static constexpr int F4R      = KCH / 4;            // 24 float4 per staged row

static constexpr int SA = 100;                       // row stride (floats): banks 4row+k, conflict-free
static constexpr int A_ARR   = ROWS_CTA * SA * 4;    // 12800 B per array (r or m)
static constexpr int B_ARR   = NPAD * SA * 4;        // 9600 B (raw W slice [n][k])
static constexpr int B_ITEMS = NPAD * F4R;           // 576 float4
static constexpr int STG_B   = 2 * A_ARR + B_ARR;    // 35200 B
static constexpr int SMEM_TOTAL = STAGES * STG_B;    // 105600 B -> 2 CTAs/SM

// epilogue aliases (after mainloop + syncthreads)
static constexpr int OFF_RED = 0;       // 2 strips * 5 slots * 36*32*4 = 46080 B
static constexpr int OFF_OUT = 46080;   // 32*20*4 = 2560 B

__device__ __forceinline__ uint32_t f2tf32(float x) {
    uint32_t t;
    asm("cvt.rna.tf32.f32 %0, %1;" : "=r"(t) : "f"(x));
    return t;
}
__device__ __forceinline__ uint32_t smem_u32(const void* p) {
    uint32_t a;
    asm("{ .reg .u64 t; cvta.to.shared.u64 t, %1; cvt.u32.u64 %0, t; }" : "=r"(a) : "l"(p));
    return a;
}
__device__ __forceinline__ void cp16(uint32_t dst, const void* src) {
    asm volatile("cp.async.cg.shared.global [%0], [%1], 16;" :: "r"(dst), "l"(src));
}
// predicated source: srcbytes=0 -> zero-fill 16 bytes (no global read)
__device__ __forceinline__ void cp16p(uint32_t dst, const void* src, int srcbytes) {
    asm volatile("cp.async.cg.shared.global [%0], [%1], 16, %2;"
                 :: "r"(dst), "l"(src), "r"(srcbytes));
}
__device__ __forceinline__ void cp_commit() {
    asm volatile("cp.async.commit_group;" ::: "memory");
}
template <int N>
__device__ __forceinline__ void cp_wait() {
    asm volatile("cp.async.wait_group %0;" :: "n"(N) : "memory");
}
__device__ __forceinline__ void mma8(float* d, const uint32_t* a, uint32_t b0, uint32_t b1) {
    asm volatile(
        "mma.sync.aligned.m16n8k8.row.col.f32.tf32.tf32.f32 "
        "{%0,%1,%2,%3}, {%4,%5,%6,%7}, {%8,%9}, {%0,%1,%2,%3};"
        : "+f"(d[0]), "+f"(d[1]), "+f"(d[2]), "+f"(d[3])
        : "r"(a[0]), "r"(a[1]), "r"(a[2]), "r"(a[3]), "r"(b0), "r"(b1));
}

__global__ void __launch_bounds__(THREADS, 2)
amatch_mma(const float* __restrict__ R, const float* __restrict__ Mx,
           const float* __restrict__ W, float* __restrict__ out)
{
    extern __shared__ char smem[];
    const uint32_t sb = smem_u32(smem);

    const int tid   = threadIdx.x;
    const int lane  = tid & 31;
    const int wid   = tid >> 5;      // 0..11
    const int g     = lane >> 2;
    const int t     = lane & 3;
    const int strip = wid / 6;       // 0/1
    const int kq    = wid % 6;       // K sixth
    const int row0  = blockIdx.x * ROWS_CTA;

    // ---- chunk-invariant staging descriptors (div/mod by 24 done ONCE) ----
    // A: items tid and tid+384 (768 float4 per array)
    const int ia0 = tid,            ia1 = tid + THREADS;
    const int ra0 = ia0 / F4R,      ra1 = ia1 / F4R;
    const int ka0 = (ia0 % F4R)<<2, ka1 = (ia1 % F4R) << 2;
    const uint32_t aso0 = (uint32_t)(ra0 * SA + ka0) * 4u;
    const uint32_t aso1 = (uint32_t)(ra1 * SA + ka1) * 4u;
    const uint32_t ago0 = (uint32_t)(ra0 * D + ka0);   // element offset, + row0*D + c*KCH
    const uint32_t ago1 = (uint32_t)(ra1 * D + ka1);
    // B: items tid and tid+384 (576 float4); second valid only for tid < 192
    const int ib0 = tid;
    const int nb0 = ib0 / F4R;
    const int kb0 = (ib0 % F4R) << 2;
    const uint32_t bso0 = (uint32_t)(2 * A_ARR) + (uint32_t)(nb0 * SA + kb0) * 4u;
    const uint32_t bgo0 = (uint32_t)(((nb0 < P) ? nb0 : 0) * D + kb0);
    const int      bbv0 = (nb0 < P) ? 16 : 0;
    const bool hasB1 = (tid < B_ITEMS - THREADS);      // tid < 192
    const int ib1 = tid + THREADS;
    const int nb1 = ib1 / F4R;
    const int kb1 = (ib1 % F4R) << 2;
    const uint32_t bso1 = (uint32_t)(2 * A_ARR) + (uint32_t)(nb1 * SA + kb1) * 4u;
    const uint32_t bgo1 = (uint32_t)(((nb1 < P) ? nb1 : 0) * D + kb1);
    const int      bbv1 = (nb1 < P) ? 16 : 0;

    const float* Rb = R  + (size_t)row0 * D;
    const float* Mb = Mx + (size_t)row0 * D;

    auto issue_stage = [&](int c, int s) {
        const uint32_t stg  = sb + (uint32_t)s * STG_B;
        const uint32_t cofs = (uint32_t)c * KCH;
        cp16(stg + aso0,         Rb + cofs + ago0);
        cp16(stg + A_ARR + aso0, Mb + cofs + ago0);
        cp16(stg + aso1,         Rb + cofs + ago1);
        cp16(stg + A_ARR + aso1, Mb + cofs + ago1);
        cp16p(stg + bso0, W + cofs + bgo0, bbv0);
        if (hasB1) cp16p(stg + bso1, W + cofs + bgo1, bbv1);
        cp_commit();
    };

    float acc[3][3][4];   // [type: rm/rr/mm][ntile][cfrag]
#pragma unroll
    for (int a = 0; a < 3; a++)
#pragma unroll
        for (int b = 0; b < 3; b++)
#pragma unroll
            for (int j = 0; j < 4; j++) acc[a][b][j] = 0.f;

    // prologue: fill stages 0..1
#pragma unroll
    for (int s = 0; s < STAGES - 1; s++) issue_stage(s, s);

    int sidx = 0;   // c % STAGES
    for (int c = 0; c < NCHUNK; ++c) {
        if (c < NCHUNK - 1) cp_wait<1>();
        else                cp_wait<0>();
        __syncthreads();

        if (c + STAGES - 1 < NCHUNK) {
            int s2 = sidx + STAGES - 1;
            if (s2 >= STAGES) s2 -= STAGES;
            issue_stage(c + STAGES - 1, s2);
        }

        const char* stg = smem + sidx * STG_B;
        const float* sr = reinterpret_cast<const float*>(stg);
        const float* sm = reinterpret_cast<const float*>(stg + A_ARR);
        const float* sw = reinterpret_cast<const float*>(stg + 2 * A_ARR);

#pragma unroll
        for (int it = 0; it < 2; it++) {
            const int kl = kq * 16 + it * 8 + t;   // k within chunk

            const int i0 = (strip * 16 + g) * SA + kl;
            const int i1 = i0 + 8 * SA;
            const float r0 = sr[i0], r1 = sr[i1], r2 = sr[i0 + 4], r3 = sr[i1 + 4];
            const float m0 = sm[i0], m1 = sm[i1], m2 = sm[i0 + 4], m3 = sm[i1 + 4];

            uint32_t arm[4] = { f2tf32(r0 * m0), f2tf32(r1 * m1), f2tf32(r2 * m2), f2tf32(r3 * m3) };
            uint32_t arr[4] = { f2tf32(r0 * r0), f2tf32(r1 * r1), f2tf32(r2 * r2), f2tf32(r3 * r3) };
            uint32_t amm[4] = { f2tf32(m0 * m0), f2tf32(m1 * m1), f2tf32(m2 * m2), f2tf32(m3 * m3) };

#pragma unroll
            for (int nt = 0; nt < 3; nt++) {
                const float w0 = sw[(nt * 8 + g) * SA + kl];
                const float w1 = sw[(nt * 8 + g) * SA + kl + 4];
                const uint32_t b0 = f2tf32(w0 * w0);
                const uint32_t b1 = f2tf32(w1 * w1);
                mma8(acc[0][nt], arm, b0, b1);
                mma8(acc[1][nt], arr, b0, b1);
                mma8(acc[2][nt], amm, b0, b1);
            }
        }

        if (++sidx == STAGES) sidx = 0;
    }
    __syncthreads();   // all warps done with stage buffers before aliasing

    // ---- reduce over the 6 K-sixth warps per strip ----
    float* s_red = reinterpret_cast<float*>(smem + OFF_RED);
    if (kq > 0) {
        float* dst = s_red + (size_t)(strip * 5 + (kq - 1)) * 36 * 32 + lane;
#pragma unroll
        for (int a = 0; a < 3; a++)
#pragma unroll
            for (int b = 0; b < 3; b++)
#pragma unroll
                for (int j = 0; j < 4; j++)
                    dst[((a * 3 + b) * 4 + j) * 32] = acc[a][b][j];
    }
    __syncthreads();

    float* s_out = reinterpret_cast<float*>(smem + OFF_OUT);
    if (kq == 0) {
#pragma unroll
        for (int s2 = 0; s2 < 5; s2++) {
            const float* src = s_red + (size_t)(strip * 5 + s2) * 36 * 32 + lane;
#pragma unroll
            for (int a = 0; a < 3; a++)
#pragma unroll
                for (int b = 0; b < 3; b++)
#pragma unroll
                    for (int j = 0; j < 4; j++)
                        acc[a][b][j] += src[((a * 3 + b) * 4 + j) * 32];
        }
        const float EPS = 1e-8f;
#pragma unroll
        for (int nt = 0; nt < 3; nt++) {
#pragma unroll
            for (int j = 0; j < 4; j++) {
                const int col = nt * 8 + 2 * t + (j & 1);
                const int row = strip * 16 + g + (j >> 1) * 8;
                if (col < P) {
                    const float dot = acc[0][nt][j];
                    const float a2  = acc[1][nt][j];
                    const float b2  = acc[2][nt][j];
                    s_out[row * P + col] =
                        dot / (fmaxf(sqrtf(a2), EPS) * fmaxf(sqrtf(b2), EPS));
                }
            }
        }
    }
    __syncthreads();

    // ---- coalesced store: 640 floats = 160 float4 ----
    if (tid < ROWS_CTA * P / 4) {
        float4 v = *reinterpret_cast<float4*>(s_out + tid * 4);
        *reinterpret_cast<float4*>(out + (size_t)row0 * P + tid * 4) = v;
    }
}

extern "C" void kernel_launch(void* const* d_in, const int* in_sizes, int n_in,
                              void* d_out, int out_size)
{
    const float* repres  = (const float*)d_in[0];
    const float* max_att = (const float*)d_in[1];
    const float* weight  = (const float*)d_in[2];
    float* out = (float*)d_out;

    cudaFuncSetAttribute(amatch_mma,
                         cudaFuncAttributeMaxDynamicSharedMemorySize, SMEM_TOTAL);

    amatch_mma<<<NCTA, THREADS, SMEM_TOTAL>>>(repres, max_att, weight, out);
}